// round 1
// baseline (speedup 1.0000x reference)
#include <cuda_runtime.h>
#include <cstddef>

// Problem constants
#define BATCH 256
#define F0    40
#define KDIM  32
#define NJ    200      // output fields per layer
#define C0    1600     // F0*40
#define C1    8000     // F0*200
#define M0    8192     // BATCH*KDIM
#define KG    16       // k-group size for layer-1 pre-sum
#define M1    512      // BATCH * (KDIM/KG)

// Scratch (static __device__ arrays per harness rules)
__device__ float g_X0[(size_t)M0 * C0];   // 52.4 MB
__device__ float g_Xp[(size_t)M1 * C1];   // 16.4 MB
__device__ float g_O0[(size_t)M0 * NJ];   // 6.55 MB  out0[b,j,k] as [bk, j]
__device__ float g_O1[(size_t)BATCH * NJ];

__global__ void zero_kernel(float* p, int n) {
    int i = blockIdx.x * 256 + threadIdx.x;
    if (i < n) p[i] = 0.f;
}

// ---------------- Layer 0 producer: X0[bk, f*40+g] ----------------
__global__ void __launch_bounds__(128) prep0_kernel(
    const float* __restrict__ inp,   // [B, F0, K]
    const float* __restrict__ wq,    // [F0, K]
    const float* __restrict__ wk,
    const float* __restrict__ wv,
    float* __restrict__ X0)
{
    __shared__ float u[F0], w[F0], v[F0], Sinv[F0];
    __shared__ float E[C0];
    int bk = blockIdx.x;
    int b = bk >> 5, k = bk & 31;
    int tid = threadIdx.x;

    if (tid < F0) {
        float x = inp[(size_t)(b * F0 + tid) * KDIM + k];
        u[tid] = x * wk[tid * KDIM + k];
        w[tid] = x * wv[tid * KDIM + k];
        v[tid] = x * wq[tid * KDIM + k];   // res == inputs for layer 0
    }
    __syncthreads();
    for (int idx = tid; idx < C0; idx += 128) {
        int f = idx / 40, g = idx - f * 40;
        E[idx] = __expf(u[f] * v[g]);
    }
    __syncthreads();
    if (tid < F0) {
        float s = 0.f;
        #pragma unroll
        for (int f = 0; f < F0; f++) s += E[f * 40 + tid];
        Sinv[tid] = 1.0f / s;
    }
    __syncthreads();
    for (int idx = tid; idx < C0; idx += 128) {
        int f = idx / 40, g = idx - f * 40;
        X0[(size_t)bk * C0 + idx] = w[f] * E[idx] * Sinv[g];
    }
}

// ---------------- Layer 1 producer with k-group pre-sum ----------------
// block = (b, kg); accumulates X over KG k-slots -> Xp[b*2+kg, c]
__global__ void __launch_bounds__(256) prep1_kernel(
    const float* __restrict__ inp,
    const float* __restrict__ out0,  // [M0, NJ]
    const float* __restrict__ wq,    // [NJ, K]
    const float* __restrict__ wk,    // [F0, K]
    const float* __restrict__ wv,
    float* __restrict__ Xp)
{
    __shared__ float u[F0], w[F0], v[NJ], Sinv[NJ];
    __shared__ float Xacc[C1];
    int blk = blockIdx.x;             // 512
    int b = blk >> 1, kg = blk & 1;
    int tid = threadIdx.x;

    for (int i = tid; i < C1; i += 256) Xacc[i] = 0.f;

    for (int kk = 0; kk < KG; kk++) {
        int k = kg * KG + kk;
        __syncthreads();
        if (tid < F0) {
            float x = inp[(size_t)(b * F0 + tid) * KDIM + k];
            u[tid] = x * wk[tid * KDIM + k];
            w[tid] = x * wv[tid * KDIM + k];
        }
        if (tid < NJ) {
            v[tid] = out0[(size_t)(b * KDIM + k) * NJ + tid] * wq[tid * KDIM + k];
        }
        __syncthreads();
        for (int g = tid; g < NJ; g += 256) {
            float vg = v[g], s = 0.f;
            #pragma unroll
            for (int f = 0; f < F0; f++) s += __expf(u[f] * vg);
            Sinv[g] = 1.0f / s;
        }
        __syncthreads();
        for (int idx = tid; idx < C1; idx += 256) {
            int f = idx / NJ, g = idx - f * NJ;
            Xacc[idx] += w[f] * __expf(u[f] * v[g]) * Sinv[g];
        }
    }
    __syncthreads();
    for (int i = tid; i < C1; i += 256)
        Xp[(size_t)blk * C1 + i] = Xacc[i];
}

// ---------------- SGEMM: Out[row>>shift, j] += A[row, c0:c0+Cchunk] @ Bw ----
// BM=128, BN=64, BK=16, 128 threads, 8x8 microtile. N fixed = 200.
__global__ void __launch_bounds__(128) sgemm_kernel(
    const float* __restrict__ A,
    const float* __restrict__ Bw,    // [C, 200] row-major
    float* __restrict__ Out,         // [*, 200], pre-zeroed, atomic accum
    int lda, int Cchunk, int rowShift)
{
    __shared__ float As[16][128];
    __shared__ float Bs[16][64];
    const int m0 = blockIdx.x * 128;
    const int n0 = blockIdx.y * 64;
    const int c0 = blockIdx.z * Cchunk;
    const int tid = threadIdx.x;
    const int rg = tid >> 3;   // 0..15
    const int cg = tid & 7;    // 0..7

    float acc[8][8];
    #pragma unroll
    for (int i = 0; i < 8; i++)
        #pragma unroll
        for (int j = 0; j < 8; j++) acc[i][j] = 0.f;

    for (int kt = 0; kt < Cchunk; kt += 16) {
        // A tile: 128 rows x 16 c, vectorized float4
        #pragma unroll
        for (int r = 0; r < 4; r++) {
            int i = tid + 128 * r;
            int row = i >> 2, cq = i & 3;
            float4 a4 = *(const float4*)&A[(size_t)(m0 + row) * lda + c0 + kt + cq * 4];
            As[cq * 4 + 0][row] = a4.x;
            As[cq * 4 + 1][row] = a4.y;
            As[cq * 4 + 2][row] = a4.z;
            As[cq * 4 + 3][row] = a4.w;
        }
        // B tile: 16 c x 64 j, guard j<200
        #pragma unroll
        for (int r = 0; r < 8; r++) {
            int i = tid + 128 * r;
            int cc = i >> 6, jj = i & 63;
            int col = n0 + jj;
            Bs[cc][jj] = (col < NJ) ? Bw[(size_t)(c0 + kt + cc) * NJ + col] : 0.f;
        }
        __syncthreads();
        #pragma unroll
        for (int kc = 0; kc < 16; kc++) {
            float a[8], bb[8];
            *(float4*)&a[0]  = *(const float4*)&As[kc][rg * 8];
            *(float4*)&a[4]  = *(const float4*)&As[kc][rg * 8 + 4];
            *(float4*)&bb[0] = *(const float4*)&Bs[kc][cg * 8];
            *(float4*)&bb[4] = *(const float4*)&Bs[kc][cg * 8 + 4];
            #pragma unroll
            for (int i = 0; i < 8; i++)
                #pragma unroll
                for (int j = 0; j < 8; j++)
                    acc[i][j] += a[i] * bb[j];
        }
        __syncthreads();
    }

    #pragma unroll
    for (int i = 0; i < 8; i++) {
        int row = m0 + rg * 8 + i;
        int orow = row >> rowShift;
        #pragma unroll
        for (int j = 0; j < 8; j++) {
            int col = n0 + cg * 8 + j;
            if (col < NJ)
                atomicAdd(&Out[(size_t)orow * NJ + col], acc[i][j]);
        }
    }
}

// ---------------- Final reduce: [B, 400] ----------------
__global__ void reduce_kernel(const float* __restrict__ out0,
                              const float* __restrict__ out1,
                              float* __restrict__ res)
{
    int i = blockIdx.x * 256 + threadIdx.x;
    if (i >= BATCH * 2 * NJ) return;
    int b = i / (2 * NJ), j = i % (2 * NJ);
    if (j < NJ) {
        float s = 0.f;
        #pragma unroll
        for (int k = 0; k < KDIM; k++)
            s += out0[(size_t)(b * KDIM + k) * NJ + j];
        res[i] = s;
    } else {
        res[i] = out1[(size_t)b * NJ + (j - NJ)];
    }
}

extern "C" void kernel_launch(void* const* d_in, const int* in_sizes, int n_in,
                              void* d_out, int out_size)
{
    const float* inp = (const float*)d_in[0];
    const float* wq0 = (const float*)d_in[1];
    const float* wk0 = (const float*)d_in[2];
    const float* wv0 = (const float*)d_in[3];
    const float* cw0 = (const float*)d_in[4];
    const float* wq1 = (const float*)d_in[5];
    const float* wk1 = (const float*)d_in[6];
    const float* wv1 = (const float*)d_in[7];
    const float* cw1 = (const float*)d_in[8];
    float* out = (float*)d_out;

    float *X0, *Xp, *O0, *O1;
    cudaGetSymbolAddress((void**)&X0, g_X0);
    cudaGetSymbolAddress((void**)&Xp, g_Xp);
    cudaGetSymbolAddress((void**)&O0, g_O0);
    cudaGetSymbolAddress((void**)&O1, g_O1);

    // zero accumulators (atomically accumulated GEMM outputs)
    zero_kernel<<<(M0 * NJ + 255) / 256, 256>>>(O0, M0 * NJ);
    zero_kernel<<<(BATCH * NJ + 255) / 256, 256>>>(O1, BATCH * NJ);

    // layer 0
    prep0_kernel<<<M0, 128>>>(inp, wq0, wk0, wv0, X0);
    // M=8192 (64 tiles) x N(4 tiles) x Csplit 4 (chunk 400)
    sgemm_kernel<<<dim3(64, 4, 4), 128>>>(X0, cw0, O0, C0, 400, 0);

    // layer 1 (X pre-summed over k-groups of 16 -> M=512 rows)
    prep1_kernel<<<M1, 256>>>(inp, O0, wq1, wk1, wv1, Xp);
    // M=512 (4 tiles) x N(4 tiles) x Csplit 20 (chunk 400); row>>1 folds kg pair
    sgemm_kernel<<<dim3(4, 4, 20), 128>>>(Xp, cw1, O1, C1, 400, 1);

    // final [256, 400]
    reduce_kernel<<<(BATCH * 2 * NJ + 255) / 256, 256>>>(O0, O1, out);
}

// round 3
// speedup vs baseline: 1.3532x; 1.3532x over previous
#include <cuda_runtime.h>
#include <cuda_bf16.h>
#include <cstdint>
#include <cstddef>

#define BATCH 256
#define F0    40
#define KDIM  32
#define NJ    200
#define C0    1600
#define C1    8000
#define M0    8192
#define KG    16
#define M1    512

// ---- scratch (static __device__, per harness rules) ----
__device__ __align__(16) __nv_bfloat16 g_A0[(size_t)M0 * 2 * C0];   // [8192, 3200]  hi|lo
__device__ __align__(16) __nv_bfloat16 g_Xp[(size_t)M1 * 2 * C1];   // [512, 16000]  hi|lo
__device__ __align__(16) __nv_bfloat16 g_B0[(size_t)256 * 2 * C0];  // [256, 3200]   hi|lo (j rows, padded)
__device__ __align__(16) __nv_bfloat16 g_B1[(size_t)256 * 2 * C1];  // [256, 16000]
__device__ float g_O0[(size_t)M0 * NJ];
__device__ float g_O1[(size_t)BATCH * NJ];

// ================= helpers =================
__device__ __forceinline__ uint32_t smem_u32(const void* p) {
    uint32_t a;
    asm("{ .reg .u64 t; cvta.to.shared.u64 t, %1; cvt.u32.u64 %0, t; }" : "=r"(a) : "l"(p));
    return a;
}

__device__ __forceinline__ void ldm_x4(uint32_t* r, uint32_t addr) {
    asm volatile("ldmatrix.sync.aligned.m8n8.x4.shared.b16 {%0,%1,%2,%3}, [%4];"
        : "=r"(r[0]), "=r"(r[1]), "=r"(r[2]), "=r"(r[3]) : "r"(addr));
}

__device__ __forceinline__ void mma_bf16(float* d, const uint32_t* a, uint32_t b0, uint32_t b1) {
    asm volatile("mma.sync.aligned.m16n8k16.row.col.f32.bf16.bf16.f32 "
        "{%0,%1,%2,%3}, {%4,%5,%6,%7}, {%8,%9}, {%0,%1,%2,%3};"
        : "+f"(d[0]), "+f"(d[1]), "+f"(d[2]), "+f"(d[3])
        : "r"(a[0]), "r"(a[1]), "r"(a[2]), "r"(a[3]), "r"(b0), "r"(b1));
}

__device__ __forceinline__ void split_store(__nv_bfloat16* hi_p, __nv_bfloat16* lo_p, float v) {
    __nv_bfloat16 h = __float2bfloat16(v);
    *hi_p = h;
    *lo_p = __float2bfloat16(v - __bfloat162float(h));
}

// ================= small kernels =================
__global__ void zero_kernel(float* p, int n) {
    int i = blockIdx.x * 256 + threadIdx.x;
    if (i < n) p[i] = 0.f;
}

// transpose + bf16-split cw[C,200] -> Bt[256, 2C] (rows j, cols c; j>=200 zero)
__global__ void bprep_kernel(const float* __restrict__ cw, __nv_bfloat16* __restrict__ Bt, int C) {
    __shared__ float t[32][33];
    int cb = blockIdx.x * 32;
    int jb = blockIdx.y * 32;
    int tx = threadIdx.x & 31, ty = threadIdx.x >> 5;  // 256 threads
    #pragma unroll
    for (int r = 0; r < 32; r += 8) {
        int c = cb + ty + r;
        int j = jb + tx;
        t[ty + r][tx] = (j < NJ) ? cw[(size_t)c * NJ + j] : 0.f;
    }
    __syncthreads();
    #pragma unroll
    for (int r = 0; r < 32; r += 8) {
        int j = jb + ty + r;
        int c = cb + tx;
        float v = t[tx][ty + r];
        split_store(&Bt[(size_t)j * (2 * C) + c], &Bt[(size_t)j * (2 * C) + C + c], v);
    }
}

// ---------------- Layer 0 producer -> A0 bf16 hi|lo ----------------
__global__ void __launch_bounds__(128) prep0_kernel(
    const float* __restrict__ inp, const float* __restrict__ wq,
    const float* __restrict__ wk, const float* __restrict__ wv,
    __nv_bfloat16* __restrict__ A0)
{
    __shared__ float u[F0], w[F0], v[F0], Sinv[F0];
    __shared__ float E[C0];
    int bk = blockIdx.x;
    int b = bk >> 5, k = bk & 31;
    int tid = threadIdx.x;

    if (tid < F0) {
        float x = inp[(size_t)(b * F0 + tid) * KDIM + k];
        u[tid] = x * wk[tid * KDIM + k];
        w[tid] = x * wv[tid * KDIM + k];
        v[tid] = x * wq[tid * KDIM + k];
    }
    __syncthreads();
    for (int idx = tid; idx < C0; idx += 128) {
        int f = idx / 40, g = idx - f * 40;
        E[idx] = __expf(u[f] * v[g]);
    }
    __syncthreads();
    if (tid < F0) {
        float s = 0.f;
        #pragma unroll
        for (int f = 0; f < F0; f++) s += E[f * 40 + tid];
        Sinv[tid] = 1.0f / s;
    }
    __syncthreads();
    __nv_bfloat16* rowp = A0 + (size_t)bk * (2 * C0);
    for (int idx = tid; idx < C0; idx += 128) {
        int f = idx / 40, g = idx - f * 40;
        float val = w[f] * E[idx] * Sinv[g];
        split_store(&rowp[idx], &rowp[C0 + idx], val);
    }
}

// ---------------- Layer 1 producer (k-presum) -> Xp bf16 hi|lo ----------------
__global__ void __launch_bounds__(256) prep1_kernel(
    const float* __restrict__ inp, const float* __restrict__ out0,
    const float* __restrict__ wq, const float* __restrict__ wk,
    const float* __restrict__ wv, __nv_bfloat16* __restrict__ Xp)
{
    extern __shared__ float dsm[];     // E[8000] | Xacc[8000]
    float* E = dsm;
    float* Xacc = dsm + C1;
    __shared__ float u[F0], w[F0], v[NJ], Sinv[NJ];
    int blk = blockIdx.x;              // 512
    int b = blk >> 1, kg = blk & 1;
    int tid = threadIdx.x;

    for (int i = tid; i < C1; i += 256) Xacc[i] = 0.f;

    for (int kk = 0; kk < KG; kk++) {
        int k = kg * KG + kk;
        __syncthreads();
        if (tid < F0) {
            float x = inp[(size_t)(b * F0 + tid) * KDIM + k];
            u[tid] = x * wk[tid * KDIM + k];
            w[tid] = x * wv[tid * KDIM + k];
        }
        if (tid < NJ) {
            v[tid] = out0[(size_t)(b * KDIM + k) * NJ + tid] * wq[tid * KDIM + k];
        }
        __syncthreads();
        if (tid < NJ) {
            float vg = v[tid], ssum = 0.f;
            #pragma unroll
            for (int f = 0; f < F0; f++) {
                float e = __expf(u[f] * vg);
                E[f * NJ + tid] = e;
                ssum += e;
            }
            Sinv[tid] = 1.0f / ssum;
        }
        __syncthreads();
        for (int idx = tid; idx < C1; idx += 256) {
            int f = idx / NJ, g = idx - f * NJ;
            Xacc[idx] += w[f] * E[idx] * Sinv[g];
        }
    }
    __syncthreads();
    __nv_bfloat16* rowp = Xp + (size_t)blk * (2 * C1);
    for (int i = tid; i < C1; i += 256)
        split_store(&rowp[i], &rowp[C1 + i], Xacc[i]);
}

// ---------------- mma.sync bf16x3 GEMM ----------------
// A [Mtot, 2K] bf16 (hi|lo), B [256, 2K] bf16 (hi|lo, rows=j padded to 256).
// Effective K = 3K via 64-k chunks: region 0 = (Ahi,Bhi), 1 = (Alo,Bhi), 2 = (Ahi,Blo).
// Block tile 128(M) x 64(N), 8 warps (4x2), warp tile 32x32, k-step 64, double-buffered.
// Out[row>>rowShift, j<200] += D (atomic, split-K safe).
__global__ void __launch_bounds__(256) mma_gemm_kernel(
    const __nv_bfloat16* __restrict__ A,
    const __nv_bfloat16* __restrict__ B,
    float* __restrict__ Out,
    int K, int cpz, int nc, int rowShift)
{
    extern __shared__ char sm[];       // 2 stages x (A 16KB + B 8KB) = 48KB
    const int tid = threadIdx.x;
    const int lane = tid & 31;
    const int wid = tid >> 5;
    const int wm0 = (wid & 3) * 32;
    const int wn0 = (wid >> 2) * 32;
    const int m0 = blockIdx.x * 128;
    const int n0 = blockIdx.y * 64;
    const int cpk = K / 64;
    const int lda = 2 * K;
    const int c0 = blockIdx.z * cpz;
    int c1 = c0 + cpz; if (c1 > nc) c1 = nc;

    const uint32_t sb = smem_u32(sm);

    float acc[2][4][4];
    #pragma unroll
    for (int i = 0; i < 2; i++)
        #pragma unroll
        for (int j = 0; j < 4; j++)
            #pragma unroll
            for (int l = 0; l < 4; l++) acc[i][j][l] = 0.f;

    uint4 ra[4], rb[2];

    auto gload = [&](int c) {
        int region = c / cpk;
        int within = c - region * cpk;
        int acol = (region == 1 ? K : 0) + within * 64;
        int bcol = (region == 2 ? K : 0) + within * 64;
        #pragma unroll
        for (int i = 0; i < 4; i++) {
            int idx = tid + 256 * i;
            ra[i] = *reinterpret_cast<const uint4*>(
                A + (size_t)(m0 + (idx >> 3)) * lda + acol + (idx & 7) * 8);
        }
        #pragma unroll
        for (int i = 0; i < 2; i++) {
            int idx = tid + 256 * i;
            rb[i] = *reinterpret_cast<const uint4*>(
                B + (size_t)(n0 + (idx >> 3)) * lda + bcol + (idx & 7) * 8);
        }
    };
    auto sstore = [&](int st) {
        char* ap = sm + st * 24576;
        char* bp = ap + 16384;
        #pragma unroll
        for (int i = 0; i < 4; i++) {
            int idx = tid + 256 * i;
            int row = idx >> 3, q = idx & 7;
            *reinterpret_cast<uint4*>(ap + (row * 8 + (q ^ (row & 7))) * 16) = ra[i];
        }
        #pragma unroll
        for (int i = 0; i < 2; i++) {
            int idx = tid + 256 * i;
            int row = idx >> 3, q = idx & 7;
            *reinterpret_cast<uint4*>(bp + (row * 8 + (q ^ (row & 7))) * 16) = rb[i];
        }
    };

    gload(c0);
    sstore(0);
    __syncthreads();

    const int t3 = lane >> 3;   // 0..3 (ldmatrix tile id)
    const int r8 = lane & 7;

    for (int c = c0; c < c1; c++) {
        int st = (c - c0) & 1;
        if (c + 1 < c1) gload(c + 1);
        uint32_t ab = sb + st * 24576;
        uint32_t bb = ab + 16384;
        #pragma unroll
        for (int ks = 0; ks < 4; ks++) {
            int kc = ks * 2;    // 16B-chunk index of this k16 step
            uint32_t afr[2][4], bfr[2][4];
            // A frags: tiles {(m+0,kc),(m+8,kc),(m+0,kc+1),(m+8,kc+1)}
            #pragma unroll
            for (int mt = 0; mt < 2; mt++) {
                int m = wm0 + mt * 16 + (t3 & 1) * 8 + r8;
                int q = kc + (t3 >> 1);
                ldm_x4(afr[mt], ab + (m * 8 + (q ^ (m & 7))) * 16);
            }
            // B frags: tiles {(n+0,kc),(n+0,kc+1),(n+8,kc),(n+8,kc+1)}
            #pragma unroll
            for (int np = 0; np < 2; np++) {
                int n = wn0 + np * 16 + (t3 >> 1) * 8 + r8;
                int q = kc + (t3 & 1);
                ldm_x4(bfr[np], bb + (n * 8 + (q ^ (n & 7))) * 16);
            }
            #pragma unroll
            for (int mt = 0; mt < 2; mt++)
                #pragma unroll
                for (int nt = 0; nt < 4; nt++)
                    mma_bf16(acc[mt][nt], afr[mt],
                             bfr[nt >> 1][(nt & 1) * 2], bfr[nt >> 1][(nt & 1) * 2 + 1]);
        }
        if (c + 1 < c1) {
            __syncthreads();
            sstore(st ^ 1);
            __syncthreads();
        }
    }

    // epilogue: atomic accumulate (split-K)
    const int g = lane >> 2, t = lane & 3;
    #pragma unroll
    for (int mt = 0; mt < 2; mt++) {
        #pragma unroll
        for (int nt = 0; nt < 4; nt++) {
            int row = m0 + wm0 + mt * 16 + g;
            int col = n0 + wn0 + nt * 8 + t * 2;
            int or0 = row >> rowShift;
            int or1 = (row + 8) >> rowShift;
            if (col < NJ) {
                atomicAdd(&Out[(size_t)or0 * NJ + col], acc[mt][nt][0]);
                atomicAdd(&Out[(size_t)or1 * NJ + col], acc[mt][nt][2]);
            }
            if (col + 1 < NJ) {
                atomicAdd(&Out[(size_t)or0 * NJ + col + 1], acc[mt][nt][1]);
                atomicAdd(&Out[(size_t)or1 * NJ + col + 1], acc[mt][nt][3]);
            }
        }
    }
}

// ---------------- Final reduce ----------------
__global__ void reduce_kernel(const float* __restrict__ out0,
                              const float* __restrict__ out1,
                              float* __restrict__ res)
{
    int i = blockIdx.x * 256 + threadIdx.x;
    if (i >= BATCH * 2 * NJ) return;
    int b = i / (2 * NJ), j = i % (2 * NJ);
    if (j < NJ) {
        float s = 0.f;
        #pragma unroll
        for (int k = 0; k < KDIM; k++)
            s += out0[(size_t)(b * KDIM + k) * NJ + j];
        res[i] = s;
    } else {
        res[i] = out1[(size_t)b * NJ + (j - NJ)];
    }
}

extern "C" void kernel_launch(void* const* d_in, const int* in_sizes, int n_in,
                              void* d_out, int out_size)
{
    const float* inp = (const float*)d_in[0];
    const float* wq0 = (const float*)d_in[1];
    const float* wk0 = (const float*)d_in[2];
    const float* wv0 = (const float*)d_in[3];
    const float* cw0 = (const float*)d_in[4];
    const float* wq1 = (const float*)d_in[5];
    const float* wk1 = (const float*)d_in[6];
    const float* wv1 = (const float*)d_in[7];
    const float* cw1 = (const float*)d_in[8];
    float* out = (float*)d_out;

    __nv_bfloat16 *A0, *Xp, *B0, *B1;
    float *O0, *O1;
    cudaGetSymbolAddress((void**)&A0, g_A0);
    cudaGetSymbolAddress((void**)&Xp, g_Xp);
    cudaGetSymbolAddress((void**)&B0, g_B0);
    cudaGetSymbolAddress((void**)&B1, g_B1);
    cudaGetSymbolAddress((void**)&O0, g_O0);
    cudaGetSymbolAddress((void**)&O1, g_O1);

    cudaFuncSetAttribute(mma_gemm_kernel, cudaFuncAttributeMaxDynamicSharedMemorySize, 49152);
    cudaFuncSetAttribute(prep1_kernel, cudaFuncAttributeMaxDynamicSharedMemorySize, 2 * C1 * 4);

    zero_kernel<<<(M0 * NJ + 255) / 256, 256>>>(O0, M0 * NJ);
    zero_kernel<<<(BATCH * NJ + 255) / 256, 256>>>(O1, BATCH * NJ);

    // weight transpose + bf16 split
    bprep_kernel<<<dim3(C0 / 32, 8), 256>>>(cw0, B0, C0);
    bprep_kernel<<<dim3(C1 / 32, 8), 256>>>(cw1, B1, C1);

    // layer 0
    prep0_kernel<<<M0, 128>>>(inp, wq0, wk0, wv0, A0);
    // M=8192 (64 tiles), N pad 256 (4 tiles), nc=75 chunks, z=3 (cpz=25)
    mma_gemm_kernel<<<dim3(64, 4, 3), 256, 49152>>>(A0, B0, O0, C0, 25, 75, 0);

    // layer 1 (k-presummed)
    prep1_kernel<<<M1, 256, 2 * C1 * 4>>>(inp, O0, wq1, wk1, wv1, Xp);
    // M=512 (4 tiles), nc=375 chunks, z=15 (cpz=25); row>>1 folds kg pair
    mma_gemm_kernel<<<dim3(4, 4, 15), 256, 49152>>>(Xp, B1, O1, C1, 25, 375, 1);

    reduce_kernel<<<(BATCH * 2 * NJ + 255) / 256, 256>>>(O0, O1, out);
}

// round 4
// speedup vs baseline: 1.6137x; 1.1925x over previous
#include <cuda_runtime.h>
#include <cuda_bf16.h>
#include <cstdint>
#include <cstddef>

#define BATCH 256
#define F0    40
#define KDIM  32
#define NJ    200
#define C0    1600
#define C1    8000
#define M0    8192
#define KG    16
#define M1    512

// ---- scratch (static __device__, per harness rules) ----
__device__ __align__(16) __nv_bfloat16 g_A0[(size_t)M0 * 2 * C0];   // [8192, 3200]  hi|lo
__device__ __align__(16) __nv_bfloat16 g_Xp[(size_t)M1 * 2 * C1];   // [512, 16000]  hi|lo
__device__ __align__(16) __nv_bfloat16 g_B0[(size_t)256 * 2 * C0];  // [256, 3200]   hi|lo
__device__ __align__(16) __nv_bfloat16 g_B1[(size_t)256 * 2 * C1];  // [256, 16000]
__device__ float g_O0[(size_t)M0 * NJ];
__device__ float g_O1[(size_t)BATCH * NJ];

// ================= helpers =================
__device__ __forceinline__ uint32_t smem_u32(const void* p) {
    uint32_t a;
    asm("{ .reg .u64 t; cvta.to.shared.u64 t, %1; cvt.u32.u64 %0, t; }" : "=r"(a) : "l"(p));
    return a;
}

__device__ __forceinline__ void ldm_x4(uint32_t* r, uint32_t addr) {
    asm volatile("ldmatrix.sync.aligned.m8n8.x4.shared.b16 {%0,%1,%2,%3}, [%4];"
        : "=r"(r[0]), "=r"(r[1]), "=r"(r[2]), "=r"(r[3]) : "r"(addr));
}

__device__ __forceinline__ void mma_bf16(float* d, const uint32_t* a, uint32_t b0, uint32_t b1) {
    asm volatile("mma.sync.aligned.m16n8k16.row.col.f32.bf16.bf16.f32 "
        "{%0,%1,%2,%3}, {%4,%5,%6,%7}, {%8,%9}, {%0,%1,%2,%3};"
        : "+f"(d[0]), "+f"(d[1]), "+f"(d[2]), "+f"(d[3])
        : "r"(a[0]), "r"(a[1]), "r"(a[2]), "r"(a[3]), "r"(b0), "r"(b1));
}

__device__ __forceinline__ void cp16(uint32_t saddr, const void* gaddr) {
    asm volatile("cp.async.cg.shared.global [%0], [%1], 16;" :: "r"(saddr), "l"(gaddr));
}
__device__ __forceinline__ void cp_commit() { asm volatile("cp.async.commit_group;" ::: "memory"); }
__device__ __forceinline__ void cp_wait0()  { asm volatile("cp.async.wait_group 0;" ::: "memory"); }

__device__ __forceinline__ void split_store(__nv_bfloat16* hi_p, __nv_bfloat16* lo_p, float v) {
    __nv_bfloat16 h = __float2bfloat16(v);
    *hi_p = h;
    *lo_p = __float2bfloat16(v - __bfloat162float(h));
}

// ================= small kernels =================
__global__ void zero_kernel(float* p, int n) {
    int i = blockIdx.x * 256 + threadIdx.x;
    if (i < n) p[i] = 0.f;
}

// transpose + bf16-split cw[C,200] -> Bt[256, 2C]
__global__ void bprep_kernel(const float* __restrict__ cw, __nv_bfloat16* __restrict__ Bt, int C) {
    __shared__ float t[32][33];
    int cb = blockIdx.x * 32;
    int jb = blockIdx.y * 32;
    int tx = threadIdx.x & 31, ty = threadIdx.x >> 5;
    #pragma unroll
    for (int r = 0; r < 32; r += 8) {
        int c = cb + ty + r;
        int j = jb + tx;
        t[ty + r][tx] = (j < NJ) ? cw[(size_t)c * NJ + j] : 0.f;
    }
    __syncthreads();
    #pragma unroll
    for (int r = 0; r < 32; r += 8) {
        int j = jb + ty + r;
        int c = cb + tx;
        float v = t[tx][ty + r];
        split_store(&Bt[(size_t)j * (2 * C) + c], &Bt[(size_t)j * (2 * C) + C + c], v);
    }
}

// ---------------- Layer 0 producer -> A0 bf16 hi|lo ----------------
__global__ void __launch_bounds__(128) prep0_kernel(
    const float* __restrict__ inp, const float* __restrict__ wq,
    const float* __restrict__ wk, const float* __restrict__ wv,
    __nv_bfloat16* __restrict__ A0)
{
    __shared__ float u[F0], w[F0], v[F0], Sinv[F0];
    __shared__ float E[C0];
    int bk = blockIdx.x;
    int b = bk >> 5, k = bk & 31;
    int tid = threadIdx.x;

    if (tid < F0) {
        float x = inp[(size_t)(b * F0 + tid) * KDIM + k];
        u[tid] = x * wk[tid * KDIM + k];
        w[tid] = x * wv[tid * KDIM + k];
        v[tid] = x * wq[tid * KDIM + k];
    }
    __syncthreads();
    for (int idx = tid; idx < C0; idx += 128) {
        int f = idx / 40, g = idx - f * 40;
        E[idx] = __expf(u[f] * v[g]);
    }
    __syncthreads();
    if (tid < F0) {
        float s = 0.f;
        #pragma unroll
        for (int f = 0; f < F0; f++) s += E[f * 40 + tid];
        Sinv[tid] = 1.0f / s;
    }
    __syncthreads();
    __nv_bfloat16* rowp = A0 + (size_t)bk * (2 * C0);
    for (int idx = tid; idx < C0; idx += 128) {
        int f = idx / 40, g = idx - f * 40;
        float val = w[f] * E[idx] * Sinv[g];
        split_store(&rowp[idx], &rowp[C0 + idx], val);
    }
}

// ---------------- Layer 1 producer: split-g, register-accumulated ----------------
// block = (b, kg, gq): gq selects a 50-wide g range. 2048 blocks x 256 threads.
// Each thread owns up to 8 (f,g) cells; accumulates over KG k-slots in registers.
__global__ void __launch_bounds__(256) prep1_kernel(
    const float* __restrict__ inp, const float* __restrict__ out0,
    const float* __restrict__ wq, const float* __restrict__ wk,
    const float* __restrict__ wv, __nv_bfloat16* __restrict__ Xp)
{
    __shared__ float u[F0], w[F0], vl[50], Sinv[50];
    __shared__ float E[2000];         // [f*50 + g_local]
    const int blk = blockIdx.x;       // 2048
    const int gq = blk & 3;
    const int bk2 = blk >> 2;
    const int kg = bk2 & 1;
    const int b = bk2 >> 1;
    const int tid = threadIdx.x;
    const int gbase = gq * 50;

    int fi[8], gi[8];
    bool ok[8];
    float acc[8];
    #pragma unroll
    for (int i = 0; i < 8; i++) {
        int id = tid + 256 * i;
        ok[i] = (id < 2000);
        int idc = ok[i] ? id : 0;
        fi[i] = idc / 50;
        gi[i] = idc - fi[i] * 50;
        acc[i] = 0.f;
    }

    for (int kk = 0; kk < KG; kk++) {
        int k = kg * KG + kk;
        __syncthreads();               // protect prior-iter smem reads
        if (tid < F0) {
            float x = inp[(size_t)(b * F0 + tid) * KDIM + k];
            u[tid] = x * wk[tid * KDIM + k];
            w[tid] = x * wv[tid * KDIM + k];
        }
        if (tid >= 64 && tid < 114) {
            int g = tid - 64;
            vl[g] = out0[(size_t)(b * KDIM + k) * NJ + gbase + g] * wq[(gbase + g) * KDIM + k];
        }
        __syncthreads();
        float e[8];
        #pragma unroll
        for (int i = 0; i < 8; i++) {
            e[i] = __expf(u[fi[i]] * vl[gi[i]]);
            if (ok[i]) E[tid + 256 * i] = e[i];
        }
        __syncthreads();
        if (tid < 50) {
            float s = 0.f;
            #pragma unroll
            for (int f = 0; f < F0; f++) s += E[f * 50 + tid];
            Sinv[tid] = 1.0f / s;
        }
        __syncthreads();
        #pragma unroll
        for (int i = 0; i < 8; i++)
            acc[i] += w[fi[i]] * e[i] * Sinv[gi[i]];
    }

    __nv_bfloat16* rowp = Xp + (size_t)(b * 2 + kg) * (2 * C1);
    #pragma unroll
    for (int i = 0; i < 8; i++) {
        if (!ok[i]) continue;
        int c = fi[i] * NJ + gbase + gi[i];
        split_store(&rowp[c], &rowp[C1 + c], acc[i]);
    }
}

// ---------------- mma.sync bf16x3 GEMM, 128x128 tile, cp.async pipeline ----------
// A [Mtot, 2K] bf16 (hi|lo), B [256, 2K] bf16 (hi|lo).
// Effective K = 3K via 64-k chunks: region 0=(Ahi,Bhi), 1=(Alo,Bhi), 2=(Ahi,Blo).
// 8 warps as 4(M) x 2(N); warp tile 32x64. Out[row>>rowShift, j<200] += D.
__global__ void __launch_bounds__(256) mma_gemm_kernel(
    const __nv_bfloat16* __restrict__ A,
    const __nv_bfloat16* __restrict__ B,
    float* __restrict__ Out,
    int K, int cpz, int nc, int rowShift)
{
    extern __shared__ char sm[];       // 2 stages x (A 16KB + B 16KB) = 64KB
    const int tid = threadIdx.x;
    const int lane = tid & 31;
    const int wid = tid >> 5;
    const int wm0 = (wid & 3) * 32;
    const int wn0 = (wid >> 2) * 64;
    const int m0 = blockIdx.x * 128;
    const int n0 = blockIdx.y * 128;
    const int cpk = K / 64;
    const int lda = 2 * K;
    const int c0 = blockIdx.z * cpz;
    int c1 = c0 + cpz; if (c1 > nc) c1 = nc;

    const uint32_t sb = smem_u32(sm);

    float acc[2][8][4];
    #pragma unroll
    for (int i = 0; i < 2; i++)
        #pragma unroll
        for (int j = 0; j < 8; j++)
            #pragma unroll
            for (int l = 0; l < 4; l++) acc[i][j][l] = 0.f;

    // issue cp.async loads of chunk c into stage st
    auto gissue = [&](int c, int st) {
        int region = c / cpk;
        int within = c - region * cpk;
        int acol = (region == 1 ? K : 0) + within * 64;
        int bcol = (region == 2 ? K : 0) + within * 64;
        uint32_t abase = sb + st * 32768;
        uint32_t bbase = abase + 16384;
        #pragma unroll
        for (int i = 0; i < 4; i++) {
            int idx = tid + 256 * i;
            int row = idx >> 3, q = idx & 7;
            cp16(abase + (row * 8 + (q ^ (row & 7))) * 16,
                 A + (size_t)(m0 + row) * lda + acol + q * 8);
        }
        #pragma unroll
        for (int i = 0; i < 4; i++) {
            int idx = tid + 256 * i;
            int row = idx >> 3, q = idx & 7;
            cp16(bbase + (row * 8 + (q ^ (row & 7))) * 16,
                 B + (size_t)(n0 + row) * lda + bcol + q * 8);
        }
        cp_commit();
    };

    gissue(c0, 0);
    cp_wait0();
    __syncthreads();

    const int t3 = lane >> 3;
    const int r8 = lane & 7;

    for (int c = c0; c < c1; c++) {
        int st = (c - c0) & 1;
        if (c + 1 < c1) gissue(c + 1, st ^ 1);
        uint32_t ab = sb + st * 32768;
        uint32_t bb = ab + 16384;
        #pragma unroll
        for (int ks = 0; ks < 4; ks++) {
            int kc = ks * 2;
            uint32_t afr[2][4], bfr[4][4];
            #pragma unroll
            for (int mt = 0; mt < 2; mt++) {
                int m = wm0 + mt * 16 + (t3 & 1) * 8 + r8;
                int q = kc + (t3 >> 1);
                ldm_x4(afr[mt], ab + (m * 8 + (q ^ (m & 7))) * 16);
            }
            #pragma unroll
            for (int np = 0; np < 4; np++) {
                int n = wn0 + np * 16 + (t3 >> 1) * 8 + r8;
                int q = kc + (t3 & 1);
                ldm_x4(bfr[np], bb + (n * 8 + (q ^ (n & 7))) * 16);
            }
            #pragma unroll
            for (int mt = 0; mt < 2; mt++)
                #pragma unroll
                for (int nt = 0; nt < 8; nt++)
                    mma_bf16(acc[mt][nt], afr[mt],
                             bfr[nt >> 1][(nt & 1) * 2], bfr[nt >> 1][(nt & 1) * 2 + 1]);
        }
        if (c + 1 < c1) {
            cp_wait0();
            __syncthreads();
        }
    }

    // epilogue: atomic accumulate (split-K safe)
    const int g = lane >> 2, t = lane & 3;
    #pragma unroll
    for (int mt = 0; mt < 2; mt++) {
        #pragma unroll
        for (int nt = 0; nt < 8; nt++) {
            int row = m0 + wm0 + mt * 16 + g;
            int col = n0 + wn0 + nt * 8 + t * 2;
            int or0 = row >> rowShift;
            int or1 = (row + 8) >> rowShift;
            if (col < NJ) {
                atomicAdd(&Out[(size_t)or0 * NJ + col], acc[mt][nt][0]);
                atomicAdd(&Out[(size_t)or1 * NJ + col], acc[mt][nt][2]);
            }
            if (col + 1 < NJ) {
                atomicAdd(&Out[(size_t)or0 * NJ + col + 1], acc[mt][nt][1]);
                atomicAdd(&Out[(size_t)or1 * NJ + col + 1], acc[mt][nt][3]);
            }
        }
    }
}

// ---------------- Final reduce ----------------
__global__ void reduce_kernel(const float* __restrict__ out0,
                              const float* __restrict__ out1,
                              float* __restrict__ res)
{
    int i = blockIdx.x * 256 + threadIdx.x;
    if (i >= BATCH * 2 * NJ) return;
    int b = i / (2 * NJ), j = i % (2 * NJ);
    if (j < NJ) {
        float s = 0.f;
        #pragma unroll
        for (int k = 0; k < KDIM; k++)
            s += out0[(size_t)(b * KDIM + k) * NJ + j];
        res[i] = s;
    } else {
        res[i] = out1[(size_t)b * NJ + (j - NJ)];
    }
}

extern "C" void kernel_launch(void* const* d_in, const int* in_sizes, int n_in,
                              void* d_out, int out_size)
{
    const float* inp = (const float*)d_in[0];
    const float* wq0 = (const float*)d_in[1];
    const float* wk0 = (const float*)d_in[2];
    const float* wv0 = (const float*)d_in[3];
    const float* cw0 = (const float*)d_in[4];
    const float* wq1 = (const float*)d_in[5];
    const float* wk1 = (const float*)d_in[6];
    const float* wv1 = (const float*)d_in[7];
    const float* cw1 = (const float*)d_in[8];
    float* out = (float*)d_out;

    __nv_bfloat16 *A0, *Xp, *B0, *B1;
    float *O0, *O1;
    cudaGetSymbolAddress((void**)&A0, g_A0);
    cudaGetSymbolAddress((void**)&Xp, g_Xp);
    cudaGetSymbolAddress((void**)&B0, g_B0);
    cudaGetSymbolAddress((void**)&B1, g_B1);
    cudaGetSymbolAddress((void**)&O0, g_O0);
    cudaGetSymbolAddress((void**)&O1, g_O1);

    cudaFuncSetAttribute(mma_gemm_kernel, cudaFuncAttributeMaxDynamicSharedMemorySize, 65536);

    zero_kernel<<<(M0 * NJ + 255) / 256, 256>>>(O0, M0 * NJ);
    zero_kernel<<<(BATCH * NJ + 255) / 256, 256>>>(O1, BATCH * NJ);

    bprep_kernel<<<dim3(C0 / 32, 8), 256>>>(cw0, B0, C0);
    bprep_kernel<<<dim3(C1 / 32, 8), 256>>>(cw1, B1, C1);

    // layer 0
    prep0_kernel<<<M0, 128>>>(inp, wq0, wk0, wv0, A0);
    // M=8192 (64 tiles), N pad 256 (2 tiles of 128), nc=75 chunks, z=3 (cpz=25)
    mma_gemm_kernel<<<dim3(64, 2, 3), 256, 65536>>>(A0, B0, O0, C0, 25, 75, 0);

    // layer 1 (k-presummed, split-g)
    prep1_kernel<<<2048, 256>>>(inp, O0, wq1, wk1, wv1, Xp);
    // M=512 (4 tiles), nc=375 chunks, z=25 (cpz=15); row>>1 folds kg pair
    mma_gemm_kernel<<<dim3(4, 2, 25), 256, 65536>>>(Xp, B1, O1, C1, 15, 375, 1);

    reduce_kernel<<<(BATCH * 2 * NJ + 255) / 256, 256>>>(O0, O1, out);
}

// round 5
// speedup vs baseline: 1.8714x; 1.1597x over previous
#include <cuda_runtime.h>
#include <cuda_bf16.h>
#include <cstdint>
#include <cstddef>

#define BATCH 256
#define F0    40
#define KDIM  32
#define NJ    200
#define C0    1600
#define C1    8000
#define M0    8192
#define KG    16
#define M1    512
#define Z0    4      // split-K slices layer 0
#define Z1    18     // split-K slices layer 1

// ---- scratch (static __device__, per harness rules) ----
__device__ __align__(16) __nv_bfloat16 g_A0[(size_t)M0 * 2 * C0];   // [8192, 3200]  hi|lo
__device__ __align__(16) __nv_bfloat16 g_Xp[(size_t)M1 * 2 * C1];   // [512, 16000]  hi|lo
__device__ __align__(16) __nv_bfloat16 g_B0[(size_t)256 * 2 * C0];  // [256, 3200]   hi|lo
__device__ __align__(16) __nv_bfloat16 g_B1[(size_t)256 * 2 * C1];  // [256, 16000]
__device__ __align__(16) float g_P0[(size_t)Z0 * M0 * NJ];          // gemm0 partials
__device__ __align__(16) float g_P1[(size_t)Z1 * BATCH * NJ];       // gemm1 partials
__device__ __align__(16) float g_O0[(size_t)M0 * NJ];               // summed out0

// ================= helpers =================
__device__ __forceinline__ uint32_t smem_u32(const void* p) {
    uint32_t a;
    asm("{ .reg .u64 t; cvta.to.shared.u64 t, %1; cvt.u32.u64 %0, t; }" : "=r"(a) : "l"(p));
    return a;
}

__device__ __forceinline__ void ldm_x4(uint32_t* r, uint32_t addr) {
    asm volatile("ldmatrix.sync.aligned.m8n8.x4.shared.b16 {%0,%1,%2,%3}, [%4];"
        : "=r"(r[0]), "=r"(r[1]), "=r"(r[2]), "=r"(r[3]) : "r"(addr));
}

__device__ __forceinline__ void mma_bf16(float* d, const uint32_t* a, uint32_t b0, uint32_t b1) {
    asm volatile("mma.sync.aligned.m16n8k16.row.col.f32.bf16.bf16.f32 "
        "{%0,%1,%2,%3}, {%4,%5,%6,%7}, {%8,%9}, {%0,%1,%2,%3};"
        : "+f"(d[0]), "+f"(d[1]), "+f"(d[2]), "+f"(d[3])
        : "r"(a[0]), "r"(a[1]), "r"(a[2]), "r"(a[3]), "r"(b0), "r"(b1));
}

__device__ __forceinline__ void cp16(uint32_t saddr, const void* gaddr) {
    asm volatile("cp.async.cg.shared.global [%0], [%1], 16;" :: "r"(saddr), "l"(gaddr));
}
__device__ __forceinline__ void cp_commit() { asm volatile("cp.async.commit_group;" ::: "memory"); }
__device__ __forceinline__ void cp_wait1()  { asm volatile("cp.async.wait_group 1;" ::: "memory"); }

__device__ __forceinline__ void split_store(__nv_bfloat16* hi_p, __nv_bfloat16* lo_p, float v) {
    __nv_bfloat16 h = __float2bfloat16(v);
    *hi_p = h;
    *lo_p = __float2bfloat16(v - __bfloat162float(h));
}

// ================= weight prep =================
// transpose + bf16-split cw[C,200] -> Bt[256, 2C]
__global__ void bprep_kernel(const float* __restrict__ cw, __nv_bfloat16* __restrict__ Bt, int C) {
    __shared__ float t[32][33];
    int cb = blockIdx.x * 32;
    int jb = blockIdx.y * 32;
    int tx = threadIdx.x & 31, ty = threadIdx.x >> 5;
    #pragma unroll
    for (int r = 0; r < 32; r += 8) {
        int c = cb + ty + r;
        int j = jb + tx;
        t[ty + r][tx] = (j < NJ) ? cw[(size_t)c * NJ + j] : 0.f;
    }
    __syncthreads();
    #pragma unroll
    for (int r = 0; r < 32; r += 8) {
        int j = jb + ty + r;
        int c = cb + tx;
        float v = t[tx][ty + r];
        split_store(&Bt[(size_t)j * (2 * C) + c], &Bt[(size_t)j * (2 * C) + C + c], v);
    }
}

// ---------------- Layer 0 producer -> A0 bf16 hi|lo ----------------
__global__ void __launch_bounds__(128) prep0_kernel(
    const float* __restrict__ inp, const float* __restrict__ wq,
    const float* __restrict__ wk, const float* __restrict__ wv,
    __nv_bfloat16* __restrict__ A0)
{
    __shared__ float u[F0], w[F0], v[F0], Sinv[F0];
    __shared__ float E[C0];
    int bk = blockIdx.x;
    int b = bk >> 5, k = bk & 31;
    int tid = threadIdx.x;

    if (tid < F0) {
        float x = inp[(size_t)(b * F0 + tid) * KDIM + k];
        u[tid] = x * wk[tid * KDIM + k];
        w[tid] = x * wv[tid * KDIM + k];
        v[tid] = x * wq[tid * KDIM + k];
    }
    __syncthreads();
    for (int idx = tid; idx < C0; idx += 128) {
        int f = idx / 40, g = idx - f * 40;
        E[idx] = __expf(u[f] * v[g]);
    }
    __syncthreads();
    if (tid < F0) {
        float s = 0.f;
        #pragma unroll
        for (int f = 0; f < F0; f++) s += E[f * 40 + tid];
        Sinv[tid] = 1.0f / s;
    }
    __syncthreads();
    __nv_bfloat16* rowp = A0 + (size_t)bk * (2 * C0);
    for (int idx = tid; idx < C0; idx += 128) {
        int f = idx / 40, g = idx - f * 40;
        float val = w[f] * E[idx] * Sinv[g];
        split_store(&rowp[idx], &rowp[C0 + idx], val);
    }
}

// ---------------- Layer 1 producer: split-g, register-accumulated ----------------
__global__ void __launch_bounds__(256) prep1_kernel(
    const float* __restrict__ inp, const float* __restrict__ out0,
    const float* __restrict__ wq, const float* __restrict__ wk,
    const float* __restrict__ wv, __nv_bfloat16* __restrict__ Xp)
{
    __shared__ float u[F0], w[F0], vl[50], Sinv[50];
    __shared__ float E[2000];
    const int blk = blockIdx.x;       // 2048
    const int gq = blk & 3;
    const int bk2 = blk >> 2;
    const int kg = bk2 & 1;
    const int b = bk2 >> 1;
    const int tid = threadIdx.x;
    const int gbase = gq * 50;

    int fi[8], gi[8];
    bool ok[8];
    float acc[8];
    #pragma unroll
    for (int i = 0; i < 8; i++) {
        int id = tid + 256 * i;
        ok[i] = (id < 2000);
        int idc = ok[i] ? id : 0;
        fi[i] = idc / 50;
        gi[i] = idc - fi[i] * 50;
        acc[i] = 0.f;
    }

    for (int kk = 0; kk < KG; kk++) {
        int k = kg * KG + kk;
        __syncthreads();
        if (tid < F0) {
            float x = inp[(size_t)(b * F0 + tid) * KDIM + k];
            u[tid] = x * wk[tid * KDIM + k];
            w[tid] = x * wv[tid * KDIM + k];
        }
        if (tid >= 64 && tid < 114) {
            int g = tid - 64;
            vl[g] = out0[(size_t)(b * KDIM + k) * NJ + gbase + g] * wq[(gbase + g) * KDIM + k];
        }
        __syncthreads();
        float e[8];
        #pragma unroll
        for (int i = 0; i < 8; i++) {
            e[i] = __expf(u[fi[i]] * vl[gi[i]]);
            if (ok[i]) E[tid + 256 * i] = e[i];
        }
        __syncthreads();
        if (tid < 50) {
            float s = 0.f;
            #pragma unroll
            for (int f = 0; f < F0; f++) s += E[f * 50 + tid];
            Sinv[tid] = 1.0f / s;
        }
        __syncthreads();
        #pragma unroll
        for (int i = 0; i < 8; i++)
            acc[i] += w[fi[i]] * e[i] * Sinv[gi[i]];
    }

    __nv_bfloat16* rowp = Xp + (size_t)(b * 2 + kg) * (2 * C1);
    #pragma unroll
    for (int i = 0; i < 8; i++) {
        if (!ok[i]) continue;
        int c = fi[i] * NJ + gbase + gi[i];
        split_store(&rowp[c], &rowp[C1 + c], acc[i]);
    }
}

// ---------------- mma.sync bf16x3 GEMM, 128x128 tile, 3-stage cp.async ----------
// A [Mtot, 2K] bf16 (hi|lo), B [256, 2K] bf16 (hi|lo).
// Effective K = 3K via 64-k chunks: region 0=(Ahi,Bhi), 1=(Alo,Bhi), 2=(Ahi,Blo).
// Split-K slice z stores PLAIN (no atomics) into P + z*sliceStride.
// fold=1: merge row pairs (2b,2b+1) via shfl before store.
__global__ void __launch_bounds__(256) mma_gemm_kernel(
    const __nv_bfloat16* __restrict__ A,
    const __nv_bfloat16* __restrict__ B,
    float* __restrict__ P, size_t sliceStride,
    int K, int cpz, int nc, int fold)
{
    extern __shared__ char sm[];       // 3 stages x (A 16KB + B 16KB) = 96KB
    const int tid = threadIdx.x;
    const int lane = tid & 31;
    const int wid = tid >> 5;
    const int wm0 = (wid & 3) * 32;
    const int wn0 = (wid >> 2) * 64;
    const int m0 = blockIdx.x * 128;
    const int n0 = blockIdx.y * 128;
    const int cpk = K / 64;
    const int lda = 2 * K;
    const int c0 = blockIdx.z * cpz;
    int c1 = c0 + cpz; if (c1 > nc) c1 = nc;

    const uint32_t sb = smem_u32(sm);
    float* Pz = P + (size_t)blockIdx.z * sliceStride;

    float acc[2][8][4];
    #pragma unroll
    for (int i = 0; i < 2; i++)
        #pragma unroll
        for (int j = 0; j < 8; j++)
            #pragma unroll
            for (int l = 0; l < 4; l++) acc[i][j][l] = 0.f;

    auto gissue = [&](int c, int st) {
        int region = c / cpk;
        int within = c - region * cpk;
        int acol = (region == 1 ? K : 0) + within * 64;
        int bcol = (region == 2 ? K : 0) + within * 64;
        uint32_t abase = sb + st * 32768;
        uint32_t bbase = abase + 16384;
        #pragma unroll
        for (int i = 0; i < 4; i++) {
            int idx = tid + 256 * i;
            int row = idx >> 3, q = idx & 7;
            cp16(abase + (row * 8 + (q ^ (row & 7))) * 16,
                 A + (size_t)(m0 + row) * lda + acol + q * 8);
        }
        #pragma unroll
        for (int i = 0; i < 4; i++) {
            int idx = tid + 256 * i;
            int row = idx >> 3, q = idx & 7;
            cp16(bbase + (row * 8 + (q ^ (row & 7))) * 16,
                 B + (size_t)(n0 + row) * lda + bcol + q * 8);
        }
        cp_commit();
    };

    // prologue: 2 groups always committed
    if (c0 < c1) gissue(c0, 0); else cp_commit();
    if (c0 + 1 < c1) gissue(c0 + 1, 1); else cp_commit();

    const int t3 = lane >> 3;
    const int r8 = lane & 7;

    for (int c = c0; c < c1; c++) {
        int rel = c - c0;
        int st = rel % 3;
        cp_wait1();                    // group(rel) done
        __syncthreads();               // all warps finished reading stage being replaced
        if (c + 2 < c1) gissue(c + 2, (rel + 2) % 3);
        uint32_t ab = sb + st * 32768;
        uint32_t bb = ab + 16384;
        #pragma unroll
        for (int ks = 0; ks < 4; ks++) {
            int kc = ks * 2;
            uint32_t afr[2][4], bfr[4][4];
            #pragma unroll
            for (int mt = 0; mt < 2; mt++) {
                int m = wm0 + mt * 16 + (t3 & 1) * 8 + r8;
                int q = kc + (t3 >> 1);
                ldm_x4(afr[mt], ab + (m * 8 + (q ^ (m & 7))) * 16);
            }
            #pragma unroll
            for (int np = 0; np < 4; np++) {
                int n = wn0 + np * 16 + (t3 >> 1) * 8 + r8;
                int q = kc + (t3 & 1);
                ldm_x4(bfr[np], bb + (n * 8 + (q ^ (n & 7))) * 16);
            }
            #pragma unroll
            for (int mt = 0; mt < 2; mt++)
                #pragma unroll
                for (int nt = 0; nt < 8; nt++)
                    mma_bf16(acc[mt][nt], afr[mt],
                             bfr[nt >> 1][(nt & 1) * 2], bfr[nt >> 1][(nt & 1) * 2 + 1]);
        }
    }

    // epilogue: plain vectorized stores into this z-slice
    const int g = lane >> 2, t = lane & 3;
    if (!fold) {
        #pragma unroll
        for (int mt = 0; mt < 2; mt++) {
            #pragma unroll
            for (int nt = 0; nt < 8; nt++) {
                int row = m0 + wm0 + mt * 16 + g;
                int col = n0 + wn0 + nt * 8 + t * 2;
                if (col < NJ) {
                    *reinterpret_cast<float2*>(&Pz[(size_t)row * NJ + col]) =
                        make_float2(acc[mt][nt][0], acc[mt][nt][1]);
                    *reinterpret_cast<float2*>(&Pz[(size_t)(row + 8) * NJ + col]) =
                        make_float2(acc[mt][nt][2], acc[mt][nt][3]);
                }
            }
        }
    } else {
        #pragma unroll
        for (int mt = 0; mt < 2; mt++) {
            #pragma unroll
            for (int nt = 0; nt < 8; nt++) {
                float v0 = acc[mt][nt][0] + __shfl_xor_sync(0xFFFFFFFFu, acc[mt][nt][0], 4);
                float v1 = acc[mt][nt][1] + __shfl_xor_sync(0xFFFFFFFFu, acc[mt][nt][1], 4);
                float v2 = acc[mt][nt][2] + __shfl_xor_sync(0xFFFFFFFFu, acc[mt][nt][2], 4);
                float v3 = acc[mt][nt][3] + __shfl_xor_sync(0xFFFFFFFFu, acc[mt][nt][3], 4);
                int row = m0 + wm0 + mt * 16 + g;
                int col = n0 + wn0 + nt * 8 + t * 2;
                if ((g & 1) == 0 && col < NJ) {
                    int or0 = row >> 1;
                    int or1 = (row + 8) >> 1;
                    *reinterpret_cast<float2*>(&Pz[(size_t)or0 * NJ + col]) = make_float2(v0, v1);
                    *reinterpret_cast<float2*>(&Pz[(size_t)or1 * NJ + col]) = make_float2(v2, v3);
                }
            }
        }
    }
}

// ---------------- sum Z0 partial slices -> O0 (float4) ----------------
__global__ void sum4_kernel(const float* __restrict__ P, float* __restrict__ O, int n4) {
    int i = blockIdx.x * 256 + threadIdx.x;
    if (i >= n4) return;
    const float4* p = reinterpret_cast<const float4*>(P);
    float4 a = p[i];
    float4 b = p[i + n4];
    float4 c = p[i + 2 * n4];
    float4 d = p[i + 3 * n4];
    reinterpret_cast<float4*>(O)[i] =
        make_float4(a.x + b.x + c.x + d.x, a.y + b.y + c.y + d.y,
                    a.z + b.z + c.z + d.z, a.w + b.w + c.w + d.w);
}

// ---------------- Final reduce: [B, 400] ----------------
__global__ void reduce_kernel(const float* __restrict__ out0,
                              const float* __restrict__ P1,
                              float* __restrict__ res)
{
    int i = blockIdx.x * 256 + threadIdx.x;
    if (i >= BATCH * 2 * NJ) return;
    int b = i / (2 * NJ), j = i % (2 * NJ);
    if (j < NJ) {
        float s = 0.f;
        #pragma unroll
        for (int k = 0; k < KDIM; k++)
            s += out0[(size_t)(b * KDIM + k) * NJ + j];
        res[i] = s;
    } else {
        float s = 0.f;
        #pragma unroll
        for (int z = 0; z < Z1; z++)
            s += P1[(size_t)z * BATCH * NJ + (size_t)b * NJ + (j - NJ)];
        res[i] = s;
    }
}

extern "C" void kernel_launch(void* const* d_in, const int* in_sizes, int n_in,
                              void* d_out, int out_size)
{
    const float* inp = (const float*)d_in[0];
    const float* wq0 = (const float*)d_in[1];
    const float* wk0 = (const float*)d_in[2];
    const float* wv0 = (const float*)d_in[3];
    const float* cw0 = (const float*)d_in[4];
    const float* wq1 = (const float*)d_in[5];
    const float* wk1 = (const float*)d_in[6];
    const float* wv1 = (const float*)d_in[7];
    const float* cw1 = (const float*)d_in[8];
    float* out = (float*)d_out;

    __nv_bfloat16 *A0, *Xp, *B0, *B1;
    float *P0, *P1, *O0;
    cudaGetSymbolAddress((void**)&A0, g_A0);
    cudaGetSymbolAddress((void**)&Xp, g_Xp);
    cudaGetSymbolAddress((void**)&B0, g_B0);
    cudaGetSymbolAddress((void**)&B1, g_B1);
    cudaGetSymbolAddress((void**)&P0, g_P0);
    cudaGetSymbolAddress((void**)&P1, g_P1);
    cudaGetSymbolAddress((void**)&O0, g_O0);

    cudaFuncSetAttribute(mma_gemm_kernel, cudaFuncAttributeMaxDynamicSharedMemorySize, 98304);

    // weight transpose + bf16 split
    bprep_kernel<<<dim3(C0 / 32, 8), 256>>>(cw0, B0, C0);
    bprep_kernel<<<dim3(C1 / 32, 8), 256>>>(cw1, B1, C1);

    // layer 0
    prep0_kernel<<<M0, 128>>>(inp, wq0, wk0, wv0, A0);
    // M=8192 (64 tiles), 2 n-tiles, nc=75 chunks, Z0=4 (cpz=19)
    mma_gemm_kernel<<<dim3(64, 2, Z0), 256, 98304>>>(A0, B0, P0, (size_t)M0 * NJ, C0, 19, 75, 0);
    sum4_kernel<<<(M0 * NJ / 4 + 255) / 256, 256>>>(P0, O0, M0 * NJ / 4);

    // layer 1 (k-presummed, split-g)
    prep1_kernel<<<2048, 256>>>(inp, O0, wq1, wk1, wv1, Xp);
    // M=512 (4 tiles), nc=375 chunks, Z1=18 (cpz=21); rows folded in-register
    mma_gemm_kernel<<<dim3(4, 2, Z1), 256, 98304>>>(Xp, B1, P1, (size_t)BATCH * NJ, C1, 21, 375, 1);

    reduce_kernel<<<(BATCH * 2 * NJ + 255) / 256, 256>>>(O0, P1, out);
}